// round 4
// baseline (speedup 1.0000x reference)
#include <cuda_runtime.h>

#define NN 40000
#define EE 640000
#define HH 128
#define GG 256
#define CC 10
#define LL 3

// Scratch (allocation-free rule: device globals, device-code references only)
__device__ float g_agg[NN * HH];
__device__ float g_buf0[NN * HH];
__device__ float g_buf1[NN * HH];
__device__ float g_pooled[GG * HH];
__device__ float g_counts[GG];
__device__ int   g_deg[NN];
__device__ int   g_rowptr[NN + 1];
__device__ int   g_cursor[NN];
__device__ int   g_srclist[EE];

__device__ __forceinline__ const float* sel_buf(int sel, const float* x) {
    return (sel < 0) ? x : (sel == 0 ? (const float*)g_buf0 : (const float*)g_buf1);
}

// ---------------------------------------------------------------------------
// Zero per-launch state: degrees, counts, pooled
// ---------------------------------------------------------------------------
__global__ void zero_misc_kernel() {
    int i = blockIdx.x * blockDim.x + threadIdx.x;
    if (i < NN) g_deg[i] = 0;
    if (i < GG) g_counts[i] = 0.f;
    if (i < GG * HH) g_pooled[i] = 0.f;
}

// ---------------------------------------------------------------------------
// Per-graph node counts (float) + in-degree histogram (int)
// ---------------------------------------------------------------------------
__global__ void count_kernel(const int* __restrict__ batch) {
    int i = blockIdx.x * blockDim.x + threadIdx.x;
    if (i < NN) atomicAdd(&g_counts[batch[i]], 1.0f);
}

__global__ void degree_kernel(const int* __restrict__ ei) {
    int e = blockIdx.x * blockDim.x + threadIdx.x;
    if (e < EE) atomicAdd(&g_deg[ei[EE + e]], 1);
}

// ---------------------------------------------------------------------------
// Exclusive scan of g_deg -> g_rowptr (and g_cursor copy). One block.
// 1024 threads x 40 items = 40960 >= 40000.
// ---------------------------------------------------------------------------
#define SCAN_ITEMS 40
__global__ void __launch_bounds__(1024) scan_kernel() {
    __shared__ int sh[1024];
    const int t = threadIdx.x;
    const int base = t * SCAN_ITEMS;

    int s = 0;
#pragma unroll
    for (int i = 0; i < SCAN_ITEMS; i++) {
        int idx = base + i;
        if (idx < NN) s += g_deg[idx];
    }
    sh[t] = s;
    __syncthreads();

    // Hillis-Steele inclusive scan over 1024 partials
    int v = s;
    for (int d = 1; d < 1024; d <<= 1) {
        int u = (t >= d) ? sh[t - d] : 0;
        __syncthreads();
        v += u;
        sh[t] = v;
        __syncthreads();
    }
    int run = v - s;  // exclusive offset for this thread's range

#pragma unroll
    for (int i = 0; i < SCAN_ITEMS; i++) {
        int idx = base + i;
        if (idx < NN) {
            g_rowptr[idx] = run;
            g_cursor[idx] = run;
            run += g_deg[idx];
        }
    }
    if (t == 1023) g_rowptr[NN] = EE;
}

// ---------------------------------------------------------------------------
// Fill CSR src lists
// ---------------------------------------------------------------------------
__global__ void fill_kernel(const int* __restrict__ ei) {
    int e = blockIdx.x * blockDim.x + threadIdx.x;
    if (e >= EE) return;
    int s = ei[e];
    int d = ei[EE + e];
    int pos = atomicAdd(&g_cursor[d], 1);
    g_srclist[pos] = s;
}

// ---------------------------------------------------------------------------
// Aggregation as gather: agg[n] = sum_{s in inlist(n)} h[s].
// One warp per node; each lane owns one float4 (32*4 = 128 floats).
// ---------------------------------------------------------------------------
__global__ void gather_kernel(const float* __restrict__ x, int sel) {
    int gid = blockIdx.x * blockDim.x + threadIdx.x;
    int node = gid >> 5;
    int lane = gid & 31;
    if (node >= NN) return;
    const float* h = sel_buf(sel, x);

    int beg = g_rowptr[node];
    int end = g_rowptr[node + 1];
    float4 acc = make_float4(0.f, 0.f, 0.f, 0.f);
    for (int p = beg; p < end; p++) {
        int s = g_srclist[p];
        float4 v = *reinterpret_cast<const float4*>(h + (size_t)s * HH + lane * 4);
        acc.x += v.x; acc.y += v.y; acc.z += v.z; acc.w += v.w;
    }
    *reinterpret_cast<float4*>(g_agg + (size_t)node * HH + lane * 4) = acc;
}

// ---------------------------------------------------------------------------
// Fused layer GEMM: out = ( [agg | h] @ [wr ; wroot] + b_rel ) * node_scale
// M=40000 (=625*64), K=256, N=128.  BM=64, BN=128, BK=16, 8x8 per thread.
// ---------------------------------------------------------------------------
__global__ void __launch_bounds__(128)
gemm_layer(const float* __restrict__ x, int in_sel, int out_sel,
           const float* __restrict__ wr, const float* __restrict__ wroot,
           const float* __restrict__ brel,
           const int* __restrict__ batch) {
    __shared__ float As[16][64];    // [k][m]
    __shared__ float Ws[16][128];   // [k][n]

    const float* h   = sel_buf(in_sel, x);
    float*       out = (out_sel == 0) ? g_buf0 : g_buf1;

    const int tid  = threadIdx.x;
    const int trow = tid >> 4;
    const int tcol = tid & 15;
    const int row0 = blockIdx.x * 64;

    float acc[8][8];
#pragma unroll
    for (int i = 0; i < 8; i++)
#pragma unroll
        for (int j = 0; j < 8; j++) acc[i][j] = 0.f;

    for (int k0 = 0; k0 < 256; k0 += 16) {
        const float* asrc = (k0 < 128) ? (const float*)g_agg : h;
        const float* wsrc = (k0 < 128) ? wr : wroot;
        const int ks = k0 & 127;

#pragma unroll
        for (int b = 0; b < 2; b++) {
            int v  = tid * 2 + b;
            int r  = v >> 2;
            int kq = (v & 3) * 4;
            float4 t = *reinterpret_cast<const float4*>(
                asrc + (size_t)(row0 + r) * HH + ks + kq);
            As[kq + 0][r] = t.x;
            As[kq + 1][r] = t.y;
            As[kq + 2][r] = t.z;
            As[kq + 3][r] = t.w;
        }
#pragma unroll
        for (int i = 0; i < 4; i++) {
            int f  = tid + i * 128;
            int kk = f >> 5;
            int n4 = (f & 31) * 4;
            float4 t = *reinterpret_cast<const float4*>(
                wsrc + (size_t)(ks + kk) * HH + n4);
            *reinterpret_cast<float4*>(&Ws[kk][n4]) = t;
        }
        __syncthreads();

#pragma unroll
        for (int k = 0; k < 16; k++) {
            float4 a0 = *reinterpret_cast<float4*>(&As[k][trow * 8]);
            float4 a1 = *reinterpret_cast<float4*>(&As[k][trow * 8 + 4]);
            float4 w0 = *reinterpret_cast<float4*>(&Ws[k][tcol * 8]);
            float4 w1 = *reinterpret_cast<float4*>(&Ws[k][tcol * 8 + 4]);
            float a[8] = {a0.x, a0.y, a0.z, a0.w, a1.x, a1.y, a1.z, a1.w};
            float w[8] = {w0.x, w0.y, w0.z, w0.w, w1.x, w1.y, w1.z, w1.w};
#pragma unroll
            for (int i = 0; i < 8; i++)
#pragma unroll
                for (int j = 0; j < 8; j++) acc[i][j] += a[i] * w[j];
        }
        __syncthreads();
    }

    float bloc[8];
#pragma unroll
    for (int j = 0; j < 8; j++) bloc[j] = brel[tcol * 8 + j];

#pragma unroll
    for (int i = 0; i < 8; i++) {
        int row = row0 + trow * 8 + i;
        float c = g_counts[batch[row]];
        float s = (c > 0.f) ? (1.f / c) : 0.f;
        float4 o0, o1;
        o0.x = (acc[i][0] + bloc[0]) * s;
        o0.y = (acc[i][1] + bloc[1]) * s;
        o0.z = (acc[i][2] + bloc[2]) * s;
        o0.w = (acc[i][3] + bloc[3]) * s;
        o1.x = (acc[i][4] + bloc[4]) * s;
        o1.y = (acc[i][5] + bloc[5]) * s;
        o1.z = (acc[i][6] + bloc[6]) * s;
        o1.w = (acc[i][7] + bloc[7]) * s;
        float* po = out + (size_t)row * HH + tcol * 8;
        *reinterpret_cast<float4*>(po)     = o0;
        *reinterpret_cast<float4*>(po + 4) = o1;
    }
}

// ---------------------------------------------------------------------------
// Pool: pooled[batch[n]] += x[n].  One warp per node, 4 scalar atomics/lane.
// ---------------------------------------------------------------------------
__global__ void pool_kernel(const float* __restrict__ x, int sel,
                            const int* __restrict__ batch) {
    int gid = blockIdx.x * blockDim.x + threadIdx.x;
    int n = gid >> 5;
    int lane = gid & 31;
    if (n >= NN) return;
    const float* h = sel_buf(sel, x);
    int g = __ldg(&batch[n]);
    float4 v = *reinterpret_cast<const float4*>(h + (size_t)n * HH + lane * 4);
    float* dst = g_pooled + (size_t)g * HH + lane * 4;
    atomicAdd(dst + 0, v.x);
    atomicAdd(dst + 1, v.y);
    atomicAdd(dst + 2, v.z);
    atomicAdd(dst + 3, v.w);
}

// ---------------------------------------------------------------------------
// Head: mean-pool scale, relu MLP, log_softmax. One block per graph.
// ---------------------------------------------------------------------------
__global__ void __launch_bounds__(HH)
head_kernel(const float* __restrict__ w1, const float* __restrict__ b1,
            const float* __restrict__ w2, const float* __restrict__ b2,
            float* __restrict__ out) {
    __shared__ float p[HH];
    __shared__ float hv[HH];
    __shared__ float lg[CC];
    __shared__ float m_s, ls_s;

    const int g = blockIdx.x;
    const int tid = threadIdx.x;

    float c = g_counts[g];
    float inv = (c > 0.f) ? (1.f / c) : 0.f;
    p[tid] = g_pooled[g * HH + tid] * inv;
    __syncthreads();

    float acc = b1[tid];
#pragma unroll 8
    for (int k = 0; k < HH; k++) acc += p[k] * w1[k * HH + tid];
    hv[tid] = fmaxf(acc, 0.f);
    __syncthreads();

    if (tid < CC) {
        float l = b2[tid];
#pragma unroll 8
        for (int k = 0; k < HH; k++) l += hv[k] * w2[k * CC + tid];
        lg[tid] = l;
    }
    __syncthreads();

    if (tid == 0) {
        float m = lg[0];
#pragma unroll
        for (int i = 1; i < CC; i++) m = fmaxf(m, lg[i]);
        float s = 0.f;
#pragma unroll
        for (int i = 0; i < CC; i++) s += expf(lg[i] - m);
        m_s = m;
        ls_s = logf(s);
    }
    __syncthreads();
    if (tid < CC) out[g * CC + tid] = lg[tid] - m_s - ls_s;
}

// ---------------------------------------------------------------------------
extern "C" void kernel_launch(void* const* d_in, const int* in_sizes, int n_in,
                              void* d_out, int out_size) {
    const float* x      = (const float*)d_in[0];
    const int*   ei     = (const int*)d_in[1];
    const int*   batch  = (const int*)d_in[2];
    const float* w_rel  = (const float*)d_in[3];
    const float* b_rel  = (const float*)d_in[4];
    const float* w_root = (const float*)d_in[5];
    const float* w1     = (const float*)d_in[6];
    const float* b1     = (const float*)d_in[7];
    const float* w2     = (const float*)d_in[8];
    const float* b2     = (const float*)d_in[9];
    float* out = (float*)d_out;

    // Reset per-launch state, build counts + CSR (edge structure reused 3x)
    zero_misc_kernel<<<(NN + 255) / 256, 256>>>();
    count_kernel<<<(NN + 255) / 256, 256>>>(batch);
    degree_kernel<<<(EE + 255) / 256, 256>>>(ei);
    scan_kernel<<<1, 1024>>>();
    fill_kernel<<<(EE + 255) / 256, 256>>>(ei);

    // 3 GraphConv layers (sel: -1 = x, 0 = g_buf0, 1 = g_buf1)
    int cur_sel = -1;
    for (int l = 0; l < LL; l++) {
        gather_kernel<<<(NN * 32 + 255) / 256, 256>>>(x, cur_sel);
        int out_sel = l & 1;
        gemm_layer<<<NN / 64, 128>>>(x, cur_sel, out_sel,
                                     w_rel + (size_t)l * HH * HH,
                                     w_root + (size_t)l * HH * HH,
                                     b_rel + (size_t)l * HH,
                                     batch);
        cur_sel = out_sel;
    }

    // Mean-pool + MLP head
    pool_kernel<<<(NN * 32 + 255) / 256, 256>>>(x, cur_sel, batch);
    head_kernel<<<GG, HH>>>(w1, b1, w2, b2, out);
}

// round 6
// speedup vs baseline: 1.3754x; 1.3754x over previous
#include <cuda_runtime.h>

#define NN 40000
#define EE 640000
#define HH 128
#define GG 256
#define CC 10
#define LL 3

#define SB 256
#define SI 4
#define SCHUNK (SB * SI)                      // 1024
#define SNB ((NN + SCHUNK - 1) / SCHUNK)      // 40

// Scratch (allocation-free rule: device globals, device-code references only)
__device__ float g_agg[NN * HH];
__device__ float g_buf0[NN * HH];
__device__ float g_buf1[NN * HH];
__device__ float g_counts[GG];
__device__ int   g_gstart[GG + 1];
__device__ int   g_deg[NN];
__device__ int   g_rowptr[NN + 1];
__device__ int   g_cursor[NN];
__device__ int   g_srclist[EE];
__device__ int   g_part[SNB];

__device__ __forceinline__ const float* sel_buf(int sel, const float* x) {
    return (sel < 0) ? x : (sel == 0 ? (const float*)g_buf0 : (const float*)g_buf1);
}

// Packed f32x2 helpers (Blackwell)
__device__ __forceinline__ unsigned long long ffma2(unsigned long long a,
                                                    unsigned long long b,
                                                    unsigned long long c) {
    unsigned long long r;
    asm("fma.rn.f32x2 %0, %1, %2, %3;" : "=l"(r) : "l"(a), "l"(b), "l"(c));
    return r;
}
__device__ __forceinline__ unsigned long long packf2(float x) {
    unsigned long long r;
    asm("mov.b64 %0, {%1, %1};" : "=l"(r) : "f"(x));
    return r;
}
__device__ __forceinline__ void unpackf2(unsigned long long d, float& lo, float& hi) {
    asm("mov.b64 {%0, %1}, %2;" : "=f"(lo), "=f"(hi) : "l"(d));
}

// ---------------------------------------------------------------------------
// Graph bounds via binary search on sorted batch. One block, 256 threads.
// ---------------------------------------------------------------------------
__global__ void bounds_kernel(const int* __restrict__ batch) {
    int g = threadIdx.x;
    int lo = 0, hi = NN;
    while (lo < hi) {
        int m = (lo + hi) >> 1;
        if (batch[m] < g) lo = m + 1; else hi = m;
    }
    g_gstart[g] = lo;
    if (g == 0) g_gstart[GG] = NN;
    __syncthreads();
    g_counts[g] = (float)(g_gstart[g + 1] - g_gstart[g]);
}

// ---------------------------------------------------------------------------
// CSR build: zero degrees, histogram, 3-phase scan, fill
// ---------------------------------------------------------------------------
__global__ void zero_deg_kernel() {
    int i = blockIdx.x * blockDim.x + threadIdx.x;
    if (i < NN) g_deg[i] = 0;
}

__global__ void degree_kernel(const int* __restrict__ ei) {
    int e = blockIdx.x * blockDim.x + threadIdx.x;
    if (e < EE) atomicAdd(&g_deg[ei[EE + e]], 1);
}

__global__ void __launch_bounds__(SB) scan1_kernel() {
    __shared__ int wsum[SB / 32];
    const int b = blockIdx.x, t = threadIdx.x;
    const int base = b * SCHUNK + t * SI;
    const int lane = t & 31, wid = t >> 5;

    int4 v = make_int4(0, 0, 0, 0);
    if (base + SI <= NN) {
        v = *reinterpret_cast<const int4*>(&g_deg[base]);
    } else {
        if (base + 0 < NN) v.x = g_deg[base + 0];
        if (base + 1 < NN) v.y = g_deg[base + 1];
        if (base + 2 < NN) v.z = g_deg[base + 2];
        if (base + 3 < NN) v.w = g_deg[base + 3];
    }
    int s = v.x + v.y + v.z + v.w;

    int inc = s;
#pragma unroll
    for (int d = 1; d < 32; d <<= 1) {
        int u = __shfl_up_sync(0xffffffffu, inc, d);
        if (lane >= d) inc += u;
    }
    if (lane == 31) wsum[wid] = inc;
    __syncthreads();
    if (t < SB / 32) {
        int ws = wsum[t];
#pragma unroll
        for (int d = 1; d < SB / 32; d <<= 1) {
            int u = __shfl_up_sync(0xffu, ws, d);
            if (t >= d) ws += u;
        }
        wsum[t] = ws;
    }
    __syncthreads();

    int r = inc - s + (wid ? wsum[wid - 1] : 0);  // exclusive prefix
    if (base + 0 < NN) g_rowptr[base + 0] = r;  r += v.x;
    if (base + 1 < NN) g_rowptr[base + 1] = r;  r += v.y;
    if (base + 2 < NN) g_rowptr[base + 2] = r;  r += v.z;
    if (base + 3 < NN) g_rowptr[base + 3] = r;
    if (t == 0) g_part[b] = wsum[SB / 32 - 1];  // block total
}

__global__ void scan2_kernel() {
    __shared__ int sh[SNB];
    int t = threadIdx.x;
    if (t < SNB) sh[t] = g_part[t];
    __syncthreads();
    if (t == 0) {
        int run = 0;
#pragma unroll
        for (int i = 0; i < SNB; i++) { int u = sh[i]; sh[i] = run; run += u; }
    }
    __syncthreads();
    if (t < SNB) g_part[t] = sh[t];
}

__global__ void __launch_bounds__(SB) scan3_kernel() {
    const int b = blockIdx.x, t = threadIdx.x;
    const int off = g_part[b];
    const int base = b * SCHUNK + t * SI;
#pragma unroll
    for (int i = 0; i < SI; i++) {
        int idx = base + i;
        if (idx < NN) {
            int r = g_rowptr[idx] + off;
            g_rowptr[idx] = r;
            g_cursor[idx] = r;
        }
    }
    if (b == 0 && t == 0) g_rowptr[NN] = EE;
}

__global__ void fill_kernel(const int* __restrict__ ei) {
    int e = blockIdx.x * blockDim.x + threadIdx.x;
    if (e >= EE) return;
    int s = ei[e];
    int d = ei[EE + e];
    int pos = atomicAdd(&g_cursor[d], 1);
    g_srclist[pos] = s;
}

// ---------------------------------------------------------------------------
// Aggregation as gather: agg[n] = sum_{s in inlist(n)} h[s].
// One warp per node; each lane owns one float4.
// ---------------------------------------------------------------------------
__global__ void gather_kernel(const float* __restrict__ x, int sel) {
    int gid = blockIdx.x * blockDim.x + threadIdx.x;
    int node = gid >> 5;
    int lane = gid & 31;
    if (node >= NN) return;
    const float* h = sel_buf(sel, x);

    int beg = g_rowptr[node];
    int end = g_rowptr[node + 1];
    float4 acc = make_float4(0.f, 0.f, 0.f, 0.f);
    for (int p = beg; p < end; p++) {
        int s = g_srclist[p];
        float4 v = *reinterpret_cast<const float4*>(h + (size_t)s * HH + lane * 4);
        acc.x += v.x; acc.y += v.y; acc.z += v.z; acc.w += v.w;
    }
    *reinterpret_cast<float4*>(g_agg + (size_t)node * HH + lane * 4) = acc;
}

// ---------------------------------------------------------------------------
// Fused layer GEMM with packed f32x2 FFMA:
// out = ( [agg | h] @ [wr ; wroot] + b_rel ) * node_scale
// M=40000 (=625*64), K=256, N=128.  BM=64, BN=128, BK=16, 8x8 per thread.
// ---------------------------------------------------------------------------
__global__ void __launch_bounds__(128)
gemm_layer(const float* __restrict__ x, int in_sel, int out_sel,
           const float* __restrict__ wr, const float* __restrict__ wroot,
           const float* __restrict__ brel,
           const int* __restrict__ batch) {
    __shared__ __align__(16) float As[16][64];    // [k][m]
    __shared__ __align__(16) float Ws[16][128];   // [k][n]

    const float* h   = sel_buf(in_sel, x);
    float*       out = (out_sel == 0) ? g_buf0 : g_buf1;

    const int tid  = threadIdx.x;
    const int trow = tid >> 4;
    const int tcol = tid & 15;
    const int row0 = blockIdx.x * 64;

    unsigned long long acc2[8][4];
#pragma unroll
    for (int i = 0; i < 8; i++)
#pragma unroll
        for (int j = 0; j < 4; j++) acc2[i][j] = 0ull;

    for (int k0 = 0; k0 < 256; k0 += 16) {
        const float* asrc = (k0 < 128) ? (const float*)g_agg : h;
        const float* wsrc = (k0 < 128) ? wr : wroot;
        const int ks = k0 & 127;

#pragma unroll
        for (int b = 0; b < 2; b++) {
            int v  = tid * 2 + b;
            int r  = v >> 2;
            int kq = (v & 3) * 4;
            float4 t = *reinterpret_cast<const float4*>(
                asrc + (size_t)(row0 + r) * HH + ks + kq);
            As[kq + 0][r] = t.x;
            As[kq + 1][r] = t.y;
            As[kq + 2][r] = t.z;
            As[kq + 3][r] = t.w;
        }
#pragma unroll
        for (int i = 0; i < 4; i++) {
            int f  = tid + i * 128;
            int kk = f >> 5;
            int n4 = (f & 31) * 4;
            float4 t = *reinterpret_cast<const float4*>(
                wsrc + (size_t)(ks + kk) * HH + n4);
            *reinterpret_cast<float4*>(&Ws[kk][n4]) = t;
        }
        __syncthreads();

#pragma unroll
        for (int k = 0; k < 16; k++) {
            float4 a0 = *reinterpret_cast<float4*>(&As[k][trow * 8]);
            float4 a1 = *reinterpret_cast<float4*>(&As[k][trow * 8 + 4]);
            ulonglong2 wA = *reinterpret_cast<ulonglong2*>(&Ws[k][tcol * 8]);
            ulonglong2 wB = *reinterpret_cast<ulonglong2*>(&Ws[k][tcol * 8 + 4]);
            unsigned long long w2[4] = {wA.x, wA.y, wB.x, wB.y};
            float a[8] = {a0.x, a0.y, a0.z, a0.w, a1.x, a1.y, a1.z, a1.w};
#pragma unroll
            for (int i = 0; i < 8; i++) {
                unsigned long long ai = packf2(a[i]);
#pragma unroll
                for (int j = 0; j < 4; j++)
                    acc2[i][j] = ffma2(ai, w2[j], acc2[i][j]);
            }
        }
        __syncthreads();
    }

    float bloc[8];
#pragma unroll
    for (int j = 0; j < 8; j++) bloc[j] = brel[tcol * 8 + j];

#pragma unroll
    for (int i = 0; i < 8; i++) {
        int row = row0 + trow * 8 + i;
        float c = g_counts[batch[row]];
        float s = (c > 0.f) ? (1.f / c) : 0.f;
        float o[8];
#pragma unroll
        for (int j = 0; j < 4; j++) unpackf2(acc2[i][j], o[2 * j], o[2 * j + 1]);
        float4 o0, o1;
        o0.x = (o[0] + bloc[0]) * s;
        o0.y = (o[1] + bloc[1]) * s;
        o0.z = (o[2] + bloc[2]) * s;
        o0.w = (o[3] + bloc[3]) * s;
        o1.x = (o[4] + bloc[4]) * s;
        o1.y = (o[5] + bloc[5]) * s;
        o1.z = (o[6] + bloc[6]) * s;
        o1.w = (o[7] + bloc[7]) * s;
        float* po = out + (size_t)row * HH + tcol * 8;
        *reinterpret_cast<float4*>(po)     = o0;
        *reinterpret_cast<float4*>(po + 4) = o1;
    }
}

// ---------------------------------------------------------------------------
// Fused head: mean-pool over contiguous graph rows (batch sorted, no atomics),
// relu MLP, log_softmax. One block of 128 threads per graph.
// ---------------------------------------------------------------------------
__global__ void __launch_bounds__(HH)
head_kernel(const float* __restrict__ x, int sel,
            const float* __restrict__ w1, const float* __restrict__ b1,
            const float* __restrict__ w2, const float* __restrict__ b2,
            float* __restrict__ out) {
    __shared__ float p[HH];
    __shared__ float hv[HH];
    __shared__ float lg[CC];
    __shared__ float m_s, ls_s;

    const int g = blockIdx.x;
    const int tid = threadIdx.x;
    const float* h = sel_buf(sel, x);

    int lo = g_gstart[g], hi = g_gstart[g + 1];
    float inv = (hi > lo) ? (1.f / (float)(hi - lo)) : 0.f;
    float acc0 = 0.f;
    for (int r = lo; r < hi; r++) acc0 += h[(size_t)r * HH + tid];
    p[tid] = acc0 * inv;
    __syncthreads();

    float acc = b1[tid];
#pragma unroll 8
    for (int k = 0; k < HH; k++) acc += p[k] * w1[k * HH + tid];
    hv[tid] = fmaxf(acc, 0.f);
    __syncthreads();

    if (tid < CC) {
        float l = b2[tid];
#pragma unroll 8
        for (int k = 0; k < HH; k++) l += hv[k] * w2[k * CC + tid];
        lg[tid] = l;
    }
    __syncthreads();

    if (tid == 0) {
        float m = lg[0];
#pragma unroll
        for (int i = 1; i < CC; i++) m = fmaxf(m, lg[i]);
        float s = 0.f;
#pragma unroll
        for (int i = 0; i < CC; i++) s += expf(lg[i] - m);
        m_s = m;
        ls_s = logf(s);
    }
    __syncthreads();
    if (tid < CC) out[g * CC + tid] = lg[tid] - m_s - ls_s;
}

// ---------------------------------------------------------------------------
extern "C" void kernel_launch(void* const* d_in, const int* in_sizes, int n_in,
                              void* d_out, int out_size) {
    const float* x      = (const float*)d_in[0];
    const int*   ei     = (const int*)d_in[1];
    const int*   batch  = (const int*)d_in[2];
    const float* w_rel  = (const float*)d_in[3];
    const float* b_rel  = (const float*)d_in[4];
    const float* w_root = (const float*)d_in[5];
    const float* w1     = (const float*)d_in[6];
    const float* b1     = (const float*)d_in[7];
    const float* w2     = (const float*)d_in[8];
    const float* b2     = (const float*)d_in[9];
    float* out = (float*)d_out;

    // Graph bounds + counts (batch is sorted)
    bounds_kernel<<<1, GG>>>(batch);

    // CSR build (edge structure reused across 3 layers)
    zero_deg_kernel<<<(NN + 255) / 256, 256>>>();
    degree_kernel<<<(EE + 255) / 256, 256>>>(ei);
    scan1_kernel<<<SNB, SB>>>();
    scan2_kernel<<<1, 64>>>();
    scan3_kernel<<<SNB, SB>>>();
    fill_kernel<<<(EE + 255) / 256, 256>>>(ei);

    // 3 GraphConv layers (sel: -1 = x, 0 = g_buf0, 1 = g_buf1)
    int cur_sel = -1;
    for (int l = 0; l < LL; l++) {
        gather_kernel<<<(NN * 32 + 255) / 256, 256>>>(x, cur_sel);
        int out_sel = l & 1;
        gemm_layer<<<NN / 64, 128>>>(x, cur_sel, out_sel,
                                     w_rel + (size_t)l * HH * HH,
                                     w_root + (size_t)l * HH * HH,
                                     b_rel + (size_t)l * HH,
                                     batch);
        cur_sel = out_sel;
    }

    // Fused mean-pool + MLP head
    head_kernel<<<GG, HH>>>(x, cur_sel, w1, b1, w2, b2, out);
}

// round 8
// speedup vs baseline: 1.8247x; 1.3267x over previous
#include <cuda_runtime.h>

typedef unsigned int u32;

#define NN 40000
#define EE 640000
#define HH 128
#define GG 256
#define CC 10
#define LL 3

#define SB 256
#define SI 4
#define SCHUNK (SB * SI)                      // 1024
#define SNB ((NN + SCHUNK - 1) / SCHUNK)      // 40

#define MT 128                                 // GEMM M tile
#define GEMM_BLOCKS ((NN + MT - 1) / MT)       // 313

// Scratch (allocation-free rule: device globals, device-code references only)
__device__ float g_agg[NN * HH];
__device__ float g_buf0[NN * HH];
__device__ float g_buf1[NN * HH];
__device__ float g_counts[GG];
__device__ int   g_gstart[GG + 1];
__device__ int   g_deg[NN];
__device__ int   g_rowptr[NN + 1];
__device__ int   g_cursor[NN];
__device__ int   g_srclist[EE];
__device__ int   g_part[SNB];

__device__ __forceinline__ const float* sel_buf(int sel, const float* x) {
    return (sel < 0) ? x : (sel == 0 ? (const float*)g_buf0 : (const float*)g_buf1);
}

__device__ __forceinline__ u32 f2tf32(float f) {
    u32 r;
    asm("cvt.rna.tf32.f32 %0, %1;" : "=r"(r) : "f"(f));
    return r;
}

__device__ __forceinline__ void mma_tf32(float* d, const u32* a, u32 b0, u32 b1) {
    asm volatile(
        "mma.sync.aligned.m16n8k8.row.col.f32.tf32.tf32.f32 "
        "{%0,%1,%2,%3}, {%4,%5,%6,%7}, {%8,%9}, {%0,%1,%2,%3};"
        : "+f"(d[0]), "+f"(d[1]), "+f"(d[2]), "+f"(d[3])
        : "r"(a[0]), "r"(a[1]), "r"(a[2]), "r"(a[3]), "r"(b0), "r"(b1));
}

// ---------------------------------------------------------------------------
// Graph bounds via binary search on sorted batch. One block, 256 threads.
// ---------------------------------------------------------------------------
__global__ void bounds_kernel(const int* __restrict__ batch) {
    int g = threadIdx.x;
    int lo = 0, hi = NN;
    while (lo < hi) {
        int m = (lo + hi) >> 1;
        if (batch[m] < g) lo = m + 1; else hi = m;
    }
    g_gstart[g] = lo;
    if (g == 0) g_gstart[GG] = NN;
    __syncthreads();
    g_counts[g] = (float)(g_gstart[g + 1] - g_gstart[g]);
}

// ---------------------------------------------------------------------------
// CSR build: zero degrees, histogram, 3-phase scan, fill
// ---------------------------------------------------------------------------
__global__ void zero_deg_kernel() {
    int i = blockIdx.x * blockDim.x + threadIdx.x;
    if (i < NN) g_deg[i] = 0;
}

__global__ void degree_kernel(const int* __restrict__ ei) {
    int e = blockIdx.x * blockDim.x + threadIdx.x;
    if (e < EE) atomicAdd(&g_deg[ei[EE + e]], 1);
}

__global__ void __launch_bounds__(SB) scan1_kernel() {
    __shared__ int wsum[SB / 32];
    const int b = blockIdx.x, t = threadIdx.x;
    const int base = b * SCHUNK + t * SI;
    const int lane = t & 31, wid = t >> 5;

    int4 v = make_int4(0, 0, 0, 0);
    if (base + SI <= NN) {
        v = *reinterpret_cast<const int4*>(&g_deg[base]);
    } else {
        if (base + 0 < NN) v.x = g_deg[base + 0];
        if (base + 1 < NN) v.y = g_deg[base + 1];
        if (base + 2 < NN) v.z = g_deg[base + 2];
        if (base + 3 < NN) v.w = g_deg[base + 3];
    }
    int s = v.x + v.y + v.z + v.w;

    int inc = s;
#pragma unroll
    for (int d = 1; d < 32; d <<= 1) {
        int u = __shfl_up_sync(0xffffffffu, inc, d);
        if (lane >= d) inc += u;
    }
    if (lane == 31) wsum[wid] = inc;
    __syncthreads();
    if (t < SB / 32) {
        int ws = wsum[t];
#pragma unroll
        for (int d = 1; d < SB / 32; d <<= 1) {
            int u = __shfl_up_sync(0xffu, ws, d);
            if (t >= d) ws += u;
        }
        wsum[t] = ws;
    }
    __syncthreads();

    int r = inc - s + (wid ? wsum[wid - 1] : 0);
    if (base + 0 < NN) g_rowptr[base + 0] = r;  r += v.x;
    if (base + 1 < NN) g_rowptr[base + 1] = r;  r += v.y;
    if (base + 2 < NN) g_rowptr[base + 2] = r;  r += v.z;
    if (base + 3 < NN) g_rowptr[base + 3] = r;
    if (t == 0) g_part[b] = wsum[SB / 32 - 1];
}

__global__ void scan2_kernel() {
    __shared__ int sh[SNB];
    int t = threadIdx.x;
    if (t < SNB) sh[t] = g_part[t];
    __syncthreads();
    if (t == 0) {
        int run = 0;
#pragma unroll
        for (int i = 0; i < SNB; i++) { int u = sh[i]; sh[i] = run; run += u; }
    }
    __syncthreads();
    if (t < SNB) g_part[t] = sh[t];
}

__global__ void __launch_bounds__(SB) scan3_kernel() {
    const int b = blockIdx.x, t = threadIdx.x;
    const int off = g_part[b];
    const int base = b * SCHUNK + t * SI;
#pragma unroll
    for (int i = 0; i < SI; i++) {
        int idx = base + i;
        if (idx < NN) {
            int r = g_rowptr[idx] + off;
            g_rowptr[idx] = r;
            g_cursor[idx] = r;
        }
    }
    if (b == 0 && t == 0) g_rowptr[NN] = EE;
}

__global__ void fill_kernel(const int* __restrict__ ei) {
    int e = blockIdx.x * blockDim.x + threadIdx.x;
    if (e >= EE) return;
    int s = ei[e];
    int d = ei[EE + e];
    int pos = atomicAdd(&g_cursor[d], 1);
    g_srclist[pos] = s;
}

// ---------------------------------------------------------------------------
// Aggregation as gather: agg[n] = sum_{s in inlist(n)} h[s].
// One warp per node; each lane owns one float4.
// ---------------------------------------------------------------------------
__global__ void gather_kernel(const float* __restrict__ x, int sel) {
    int gid = blockIdx.x * blockDim.x + threadIdx.x;
    int node = gid >> 5;
    int lane = gid & 31;
    if (node >= NN) return;
    const float* h = sel_buf(sel, x);

    int beg = g_rowptr[node];
    int end = g_rowptr[node + 1];
    float4 acc = make_float4(0.f, 0.f, 0.f, 0.f);
    for (int p = beg; p < end; p++) {
        int s = g_srclist[p];
        float4 v = *reinterpret_cast<const float4*>(h + (size_t)s * HH + lane * 4);
        acc.x += v.x; acc.y += v.y; acc.z += v.z; acc.w += v.w;
    }
    *reinterpret_cast<float4*>(g_agg + (size_t)node * HH + lane * 4) = acc;
}

// ---------------------------------------------------------------------------
// Tensor-core layer GEMM (tf32 mma.sync, sm_80+ path — plain sm_100 safe):
// out = ( [agg | h] @ [wr ; wroot] + b_rel ) * node_scale
// Block 256 thr = 8 warps (4 M x 2 N). M-tile 128, N=128, K=256 in 8 chunks
// of 32. Per warp: 2 M-frags x 8 N-frags of m16n8k8.
// ---------------------------------------------------------------------------
__global__ void __launch_bounds__(256)
gemm_layer_mma(const float* __restrict__ x, int in_sel, int out_sel,
               const float* __restrict__ wr, const float* __restrict__ wroot,
               const float* __restrict__ brel,
               const int* __restrict__ batch) {
    __shared__ u32 As[128][36];   // stride 36: a-frag banks 4g+t4 distinct
    __shared__ u32 Bs[32][136];   // stride 136 (=8 mod 32): b-frag banks 8t4+g distinct

    const float* h   = sel_buf(in_sel, x);
    float*       out = (out_sel == 0) ? g_buf0 : g_buf1;

    const int tid  = threadIdx.x;
    const int wid  = tid >> 5, lane = tid & 31;
    const int g    = lane >> 2, t4 = lane & 3;
    const int wm   = wid & 3,  wn  = wid >> 2;
    const int row0 = blockIdx.x * MT;
    const int mbase = wm * 32;
    const int nbase = wn * 64;

    float acc[2][8][4];
#pragma unroll
    for (int mf = 0; mf < 2; mf++)
#pragma unroll
        for (int nf = 0; nf < 8; nf++)
#pragma unroll
            for (int q = 0; q < 4; q++) acc[mf][nf][q] = 0.f;

    for (int c = 0; c < 8; c++) {
        const float* asrc = (c < 4) ? (const float*)g_agg : h;
        const float* wsrc = (c < 4) ? wr : wroot;
        const int ks = (c & 3) * 32;

        __syncthreads();
        // A chunk: 128 rows x 32 k (1024 float4, 4 per thread)
#pragma unroll
        for (int i = 0; i < 4; i++) {
            int f = tid + i * 256;
            int r = f >> 3, q = f & 7;
            float4 v = make_float4(0.f, 0.f, 0.f, 0.f);
            if (row0 + r < NN)
                v = *reinterpret_cast<const float4*>(asrc + (size_t)(row0 + r) * HH + ks + q * 4);
            As[r][q * 4 + 0] = f2tf32(v.x);
            As[r][q * 4 + 1] = f2tf32(v.y);
            As[r][q * 4 + 2] = f2tf32(v.z);
            As[r][q * 4 + 3] = f2tf32(v.w);
        }
        // B chunk: 32 k rows x 128 n (1024 float4, 4 per thread), layout [k][n]
#pragma unroll
        for (int i = 0; i < 4; i++) {
            int f = tid + i * 256;
            int r = f >> 5, q = f & 31;
            float4 v = *reinterpret_cast<const float4*>(wsrc + (size_t)(ks + r) * HH + q * 4);
            Bs[r][q * 4 + 0] = f2tf32(v.x);
            Bs[r][q * 4 + 1] = f2tf32(v.y);
            Bs[r][q * 4 + 2] = f2tf32(v.z);
            Bs[r][q * 4 + 3] = f2tf32(v.w);
        }
        __syncthreads();

#pragma unroll
        for (int k8 = 0; k8 < 4; k8++) {
            const int kk = k8 * 8;
            u32 a[2][4];
#pragma unroll
            for (int mf = 0; mf < 2; mf++) {
                int rm = mbase + mf * 16;
                a[mf][0] = As[rm + g][kk + t4];
                a[mf][1] = As[rm + g + 8][kk + t4];
                a[mf][2] = As[rm + g][kk + t4 + 4];
                a[mf][3] = As[rm + g + 8][kk + t4 + 4];
            }
#pragma unroll
            for (int nf = 0; nf < 8; nf++) {
                u32 b0 = Bs[kk + t4][nbase + nf * 8 + g];
                u32 b1 = Bs[kk + t4 + 4][nbase + nf * 8 + g];
                mma_tf32(acc[0][nf], a[0], b0, b1);
                mma_tf32(acc[1][nf], a[1], b0, b1);
            }
        }
    }

    // Epilogue: +bias, *node_scale, direct stores (c0,c1 / c2,c3 pairs as float2)
#pragma unroll
    for (int mf = 0; mf < 2; mf++) {
        int r0 = row0 + mbase + mf * 16 + g;
        int r1 = r0 + 8;
        float s0 = 0.f, s1 = 0.f;
        if (r0 < NN) { float cnt = g_counts[batch[r0]]; s0 = (cnt > 0.f) ? (1.f / cnt) : 0.f; }
        if (r1 < NN) { float cnt = g_counts[batch[r1]]; s1 = (cnt > 0.f) ? (1.f / cnt) : 0.f; }
#pragma unroll
        for (int nf = 0; nf < 8; nf++) {
            int col = nbase + nf * 8 + t4 * 2;
            float b0 = __ldg(&brel[col]), b1 = __ldg(&brel[col + 1]);
            if (r0 < NN) {
                float2 o = make_float2((acc[mf][nf][0] + b0) * s0,
                                       (acc[mf][nf][1] + b1) * s0);
                *reinterpret_cast<float2*>(out + (size_t)r0 * HH + col) = o;
            }
            if (r1 < NN) {
                float2 o = make_float2((acc[mf][nf][2] + b0) * s1,
                                       (acc[mf][nf][3] + b1) * s1);
                *reinterpret_cast<float2*>(out + (size_t)r1 * HH + col) = o;
            }
        }
    }
}

// ---------------------------------------------------------------------------
// Fused head: mean-pool over contiguous graph rows, relu MLP, log_softmax.
// ---------------------------------------------------------------------------
__global__ void __launch_bounds__(HH)
head_kernel(const float* __restrict__ x, int sel,
            const float* __restrict__ w1, const float* __restrict__ b1,
            const float* __restrict__ w2, const float* __restrict__ b2,
            float* __restrict__ out) {
    __shared__ float p[HH];
    __shared__ float hv[HH];
    __shared__ float lg[CC];
    __shared__ float m_s, ls_s;

    const int g = blockIdx.x;
    const int tid = threadIdx.x;
    const float* h = sel_buf(sel, x);

    int lo = g_gstart[g], hi = g_gstart[g + 1];
    float inv = (hi > lo) ? (1.f / (float)(hi - lo)) : 0.f;
    float acc0 = 0.f;
    for (int r = lo; r < hi; r++) acc0 += h[(size_t)r * HH + tid];
    p[tid] = acc0 * inv;
    __syncthreads();

    float acc = b1[tid];
#pragma unroll 8
    for (int k = 0; k < HH; k++) acc += p[k] * w1[k * HH + tid];
    hv[tid] = fmaxf(acc, 0.f);
    __syncthreads();

    if (tid < CC) {
        float l = b2[tid];
#pragma unroll 8
        for (int k = 0; k < HH; k++) l += hv[k] * w2[k * CC + tid];
        lg[tid] = l;
    }
    __syncthreads();

    if (tid == 0) {
        float m = lg[0];
#pragma unroll
        for (int i = 1; i < CC; i++) m = fmaxf(m, lg[i]);
        float s = 0.f;
#pragma unroll
        for (int i = 0; i < CC; i++) s += expf(lg[i] - m);
        m_s = m;
        ls_s = logf(s);
    }
    __syncthreads();
    if (tid < CC) out[g * CC + tid] = lg[tid] - m_s - ls_s;
}

// ---------------------------------------------------------------------------
extern "C" void kernel_launch(void* const* d_in, const int* in_sizes, int n_in,
                              void* d_out, int out_size) {
    const float* x      = (const float*)d_in[0];
    const int*   ei     = (const int*)d_in[1];
    const int*   batch  = (const int*)d_in[2];
    const float* w_rel  = (const float*)d_in[3];
    const float* b_rel  = (const float*)d_in[4];
    const float* w_root = (const float*)d_in[5];
    const float* w1     = (const float*)d_in[6];
    const float* b1     = (const float*)d_in[7];
    const float* w2     = (const float*)d_in[8];
    const float* b2     = (const float*)d_in[9];
    float* out = (float*)d_out;

    // Graph bounds + counts (batch is sorted)
    bounds_kernel<<<1, GG>>>(batch);

    // CSR build (edge structure reused across 3 layers)
    zero_deg_kernel<<<(NN + 255) / 256, 256>>>();
    degree_kernel<<<(EE + 255) / 256, 256>>>(ei);
    scan1_kernel<<<SNB, SB>>>();
    scan2_kernel<<<1, 64>>>();
    scan3_kernel<<<SNB, SB>>>();
    fill_kernel<<<(EE + 255) / 256, 256>>>(ei);

    // 3 GraphConv layers (sel: -1 = x, 0 = g_buf0, 1 = g_buf1)
    int cur_sel = -1;
    for (int l = 0; l < LL; l++) {
        gather_kernel<<<(NN * 32 + 255) / 256, 256>>>(x, cur_sel);
        int out_sel = l & 1;
        gemm_layer_mma<<<GEMM_BLOCKS, 256>>>(x, cur_sel, out_sel,
                                             w_rel + (size_t)l * HH * HH,
                                             w_root + (size_t)l * HH * HH,
                                             b_rel + (size_t)l * HH,
                                             batch);
        cur_sel = out_sel;
    }

    // Fused mean-pool + MLP head
    head_kernel<<<GG, HH>>>(x, cur_sel, w1, b1, w2, b2, out);
}

// round 9
// speedup vs baseline: 2.5474x; 1.3961x over previous
#include <cuda_runtime.h>
#include <cuda_fp16.h>

typedef unsigned int u32;

#define NN 40000
#define EE 640000
#define HH 128
#define GG 256
#define CC 10
#define LL 3

#define SB 256
#define SI 4
#define SCHUNK (SB * SI)                      // 1024
#define SNB ((NN + SCHUNK - 1) / SCHUNK)      // 40

#define MT 128                                 // GEMM M tile
#define GEMM_BLOCKS ((NN + MT - 1) / MT)       // 313

// Scratch (allocation-free rule: device globals, device-code references only)
__device__ __half g_xh[NN * HH];
__device__ __half g_aggh[NN * HH];
__device__ __half g_h0[NN * HH];
__device__ __half g_h1[NN * HH];
__device__ __half g_wTh[6][HH * HH];   // [layer*2+(0=rel,1=root)][n][k] fp16
__device__ float g_counts[GG];
__device__ int   g_gstart[GG + 1];
__device__ int   g_deg[NN];
__device__ int   g_rowptr[NN + 1];
__device__ int   g_cursor[NN];
__device__ int   g_srclist[EE];
__device__ int   g_part[SNB];

__device__ __forceinline__ const __half* sel_buf_h(int sel) {
    return (sel < 0) ? (const __half*)g_xh
                     : (sel == 0 ? (const __half*)g_h0 : (const __half*)g_h1);
}

__device__ __forceinline__ void mma_f16(float* d, const u32* a, u32 b0, u32 b1) {
    asm volatile(
        "mma.sync.aligned.m16n8k16.row.col.f32.f16.f16.f32 "
        "{%0,%1,%2,%3}, {%4,%5,%6,%7}, {%8,%9}, {%0,%1,%2,%3};"
        : "+f"(d[0]), "+f"(d[1]), "+f"(d[2]), "+f"(d[3])
        : "r"(a[0]), "r"(a[1]), "r"(a[2]), "r"(a[3]), "r"(b0), "r"(b1));
}

// ---------------------------------------------------------------------------
// Convert x (fp32) -> g_xh (fp16). 1.28M threads, 1 float4 each.
// ---------------------------------------------------------------------------
__global__ void convert_x_kernel(const float* __restrict__ x) {
    int i = blockIdx.x * blockDim.x + threadIdx.x;
    if (i >= NN * HH / 4) return;
    float4 v = reinterpret_cast<const float4*>(x)[i];
    __half2 h0 = __floats2half2_rn(v.x, v.y);
    __half2 h1 = __floats2half2_rn(v.z, v.w);
    uint2 o = make_uint2(*(u32*)&h0, *(u32*)&h1);
    reinterpret_cast<uint2*>(g_xh)[i] = o;
}

// ---------------------------------------------------------------------------
// Transpose + convert weights: g_wTh[l*2+t][n*HH+k] = (half)w[l][k][n]
// ---------------------------------------------------------------------------
__global__ void convert_w_kernel(const float* __restrict__ w_rel,
                                 const float* __restrict__ w_root) {
    int idx = blockIdx.x * blockDim.x + threadIdx.x;
    if (idx >= 6 * HH * HH) return;
    int m = idx / (HH * HH);
    int rem = idx % (HH * HH);
    int n = rem / HH, k = rem % HH;
    int l = m >> 1;
    const float* w = (m & 1) ? (w_root + (size_t)l * HH * HH)
                             : (w_rel + (size_t)l * HH * HH);
    g_wTh[m][n * HH + k] = __float2half(w[k * HH + n]);
}

// ---------------------------------------------------------------------------
// Graph bounds via binary search on sorted batch. One block, 256 threads.
// ---------------------------------------------------------------------------
__global__ void bounds_kernel(const int* __restrict__ batch) {
    int g = threadIdx.x;
    int lo = 0, hi = NN;
    while (lo < hi) {
        int m = (lo + hi) >> 1;
        if (batch[m] < g) lo = m + 1; else hi = m;
    }
    g_gstart[g] = lo;
    if (g == 0) g_gstart[GG] = NN;
    __syncthreads();
    g_counts[g] = (float)(g_gstart[g + 1] - g_gstart[g]);
}

// ---------------------------------------------------------------------------
// CSR build: zero degrees, histogram, 3-phase scan, fill
// ---------------------------------------------------------------------------
__global__ void zero_deg_kernel() {
    int i = blockIdx.x * blockDim.x + threadIdx.x;
    if (i < NN) g_deg[i] = 0;
}

__global__ void degree_kernel(const int* __restrict__ ei) {
    int e = blockIdx.x * blockDim.x + threadIdx.x;
    if (e < EE) atomicAdd(&g_deg[ei[EE + e]], 1);
}

__global__ void __launch_bounds__(SB) scan1_kernel() {
    __shared__ int wsum[SB / 32];
    const int b = blockIdx.x, t = threadIdx.x;
    const int base = b * SCHUNK + t * SI;
    const int lane = t & 31, wid = t >> 5;

    int4 v = make_int4(0, 0, 0, 0);
    if (base + SI <= NN) {
        v = *reinterpret_cast<const int4*>(&g_deg[base]);
    } else {
        if (base + 0 < NN) v.x = g_deg[base + 0];
        if (base + 1 < NN) v.y = g_deg[base + 1];
        if (base + 2 < NN) v.z = g_deg[base + 2];
        if (base + 3 < NN) v.w = g_deg[base + 3];
    }
    int s = v.x + v.y + v.z + v.w;

    int inc = s;
#pragma unroll
    for (int d = 1; d < 32; d <<= 1) {
        int u = __shfl_up_sync(0xffffffffu, inc, d);
        if (lane >= d) inc += u;
    }
    if (lane == 31) wsum[wid] = inc;
    __syncthreads();
    if (t < SB / 32) {
        int ws = wsum[t];
#pragma unroll
        for (int d = 1; d < SB / 32; d <<= 1) {
            int u = __shfl_up_sync(0xffu, ws, d);
            if (t >= d) ws += u;
        }
        wsum[t] = ws;
    }
    __syncthreads();

    int r = inc - s + (wid ? wsum[wid - 1] : 0);
    if (base + 0 < NN) g_rowptr[base + 0] = r;  r += v.x;
    if (base + 1 < NN) g_rowptr[base + 1] = r;  r += v.y;
    if (base + 2 < NN) g_rowptr[base + 2] = r;  r += v.z;
    if (base + 3 < NN) g_rowptr[base + 3] = r;
    if (t == 0) g_part[b] = wsum[SB / 32 - 1];
}

__global__ void scan2_kernel() {
    __shared__ int sh[SNB];
    int t = threadIdx.x;
    if (t < SNB) sh[t] = g_part[t];
    __syncthreads();
    if (t == 0) {
        int run = 0;
#pragma unroll
        for (int i = 0; i < SNB; i++) { int u = sh[i]; sh[i] = run; run += u; }
    }
    __syncthreads();
    if (t < SNB) g_part[t] = sh[t];
}

__global__ void __launch_bounds__(SB) scan3_kernel() {
    const int b = blockIdx.x, t = threadIdx.x;
    const int off = g_part[b];
    const int base = b * SCHUNK + t * SI;
#pragma unroll
    for (int i = 0; i < SI; i++) {
        int idx = base + i;
        if (idx < NN) {
            int r = g_rowptr[idx] + off;
            g_rowptr[idx] = r;
            g_cursor[idx] = r;
        }
    }
    if (b == 0 && t == 0) g_rowptr[NN] = EE;
}

__global__ void fill_kernel(const int* __restrict__ ei) {
    int e = blockIdx.x * blockDim.x + threadIdx.x;
    if (e >= EE) return;
    int s = ei[e];
    int d = ei[EE + e];
    int pos = atomicAdd(&g_cursor[d], 1);
    g_srclist[pos] = s;
}

// ---------------------------------------------------------------------------
// Aggregation as gather (fp16 in, fp32 accum, fp16 out):
// one warp per node, each lane owns 4 features (8B per edge per lane).
// ---------------------------------------------------------------------------
__global__ void gather_kernel(int sel) {
    int gid = blockIdx.x * blockDim.x + threadIdx.x;
    int node = gid >> 5;
    int lane = gid & 31;
    if (node >= NN) return;
    const __half* h = sel_buf_h(sel);

    int beg = g_rowptr[node];
    int end = g_rowptr[node + 1];
    float2 accA = make_float2(0.f, 0.f);
    float2 accB = make_float2(0.f, 0.f);
    int p = beg;
    for (; p + 2 <= end; p += 2) {
        int s0 = g_srclist[p], s1 = g_srclist[p + 1];
        uint2 v0 = *reinterpret_cast<const uint2*>(h + (size_t)s0 * HH + lane * 4);
        uint2 v1 = *reinterpret_cast<const uint2*>(h + (size_t)s1 * HH + lane * 4);
        float2 a0 = __half22float2(*(__half2*)&v0.x);
        float2 a1 = __half22float2(*(__half2*)&v0.y);
        float2 b0 = __half22float2(*(__half2*)&v1.x);
        float2 b1 = __half22float2(*(__half2*)&v1.y);
        accA.x += a0.x + b0.x;  accA.y += a0.y + b0.y;
        accB.x += a1.x + b1.x;  accB.y += a1.y + b1.y;
    }
    if (p < end) {
        int s0 = g_srclist[p];
        uint2 v0 = *reinterpret_cast<const uint2*>(h + (size_t)s0 * HH + lane * 4);
        float2 a0 = __half22float2(*(__half2*)&v0.x);
        float2 a1 = __half22float2(*(__half2*)&v0.y);
        accA.x += a0.x;  accA.y += a0.y;
        accB.x += a1.x;  accB.y += a1.y;
    }
    __half2 o0 = __floats2half2_rn(accA.x, accA.y);
    __half2 o1 = __floats2half2_rn(accB.x, accB.y);
    uint2 o = make_uint2(*(u32*)&o0, *(u32*)&o1);
    *reinterpret_cast<uint2*>(g_aggh + (size_t)node * HH + lane * 4) = o;
}

// ---------------------------------------------------------------------------
// Tensor-core layer GEMM (fp16 mma.sync m16n8k16, fp32 accum):
// out = ( [agg | h] @ [wr ; wroot] + b_rel ) * node_scale   (fp16 out)
// Block 256 thr = 8 warps (4 M x 2 N). M-tile 128, N=128, K=256 in 8 chunks
// of 32 (2 k16 steps each). Per warp: 2 M-frags x 8 N-frags.
// ---------------------------------------------------------------------------
__global__ void __launch_bounds__(256)
gemm_layer_mma(int in_sel, int out_sel, int layer,
               const float* __restrict__ brel,
               const int* __restrict__ batch) {
    __shared__ __half As[128][40];   // 32 data + 8 pad halves (stride 20 words)
    __shared__ __half Bs[128][40];

    const __half* h   = sel_buf_h(in_sel);
    __half*       out = (out_sel == 0) ? (__half*)g_h0 : (__half*)g_h1;

    const int tid  = threadIdx.x;
    const int wid  = tid >> 5, lane = tid & 31;
    const int g    = lane >> 2, t4 = lane & 3;
    const int wm   = wid & 3,  wn  = wid >> 2;
    const int row0 = blockIdx.x * MT;
    const int mbase = wm * 32;
    const int nbase = wn * 64;

    float acc[2][8][4];
#pragma unroll
    for (int mf = 0; mf < 2; mf++)
#pragma unroll
        for (int nf = 0; nf < 8; nf++)
#pragma unroll
            for (int q = 0; q < 4; q++) acc[mf][nf][q] = 0.f;

    for (int c = 0; c < 8; c++) {
        const __half* asrc = (c < 4) ? (const __half*)g_aggh : h;
        const __half* bsrc = &g_wTh[layer * 2 + (c < 4 ? 0 : 1)][0];
        const int ks = (c & 3) * 32;

        __syncthreads();
        // A chunk: 128 rows x 32 halves (64B/row) = 512 x 16B, 2 per thread
#pragma unroll
        for (int i = 0; i < 2; i++) {
            int f = tid + i * 256;           // 0..511
            int r = f >> 2, q = f & 3;       // row, 16B unit
            uint4 v = make_uint4(0, 0, 0, 0);
            if (row0 + r < NN)
                v = *reinterpret_cast<const uint4*>(asrc + (size_t)(row0 + r) * HH + ks + q * 8);
            *reinterpret_cast<uint4*>(&As[r][q * 8]) = v;
        }
        // B chunk: 128 n-rows x 32 k-halves from [n][k] fp16 weights
#pragma unroll
        for (int i = 0; i < 2; i++) {
            int f = tid + i * 256;
            int r = f >> 2, q = f & 3;
            uint4 v = *reinterpret_cast<const uint4*>(bsrc + (size_t)r * HH + ks + q * 8);
            *reinterpret_cast<uint4*>(&Bs[r][q * 8]) = v;
        }
        __syncthreads();

#pragma unroll
        for (int k16 = 0; k16 < 2; k16++) {
            const int kk = k16 * 16;
            u32 a[2][4];
#pragma unroll
            for (int mf = 0; mf < 2; mf++) {
                int rm = mbase + mf * 16;
                a[mf][0] = *(const u32*)&As[rm + g][kk + 2 * t4];
                a[mf][1] = *(const u32*)&As[rm + g + 8][kk + 2 * t4];
                a[mf][2] = *(const u32*)&As[rm + g][kk + 2 * t4 + 8];
                a[mf][3] = *(const u32*)&As[rm + g + 8][kk + 2 * t4 + 8];
            }
#pragma unroll
            for (int nf = 0; nf < 8; nf++) {
                int nrow = nbase + nf * 8 + g;
                u32 b0 = *(const u32*)&Bs[nrow][kk + 2 * t4];
                u32 b1 = *(const u32*)&Bs[nrow][kk + 2 * t4 + 8];
                mma_f16(acc[0][nf], a[0], b0, b1);
                mma_f16(acc[1][nf], a[1], b0, b1);
            }
        }
    }

    // Epilogue: +bias, *node_scale (fp32), convert to fp16, 4B stores
#pragma unroll
    for (int mf = 0; mf < 2; mf++) {
        int r0 = row0 + mbase + mf * 16 + g;
        int r1 = r0 + 8;
        float s0 = 0.f, s1 = 0.f;
        if (r0 < NN) { float cnt = g_counts[batch[r0]]; s0 = (cnt > 0.f) ? (1.f / cnt) : 0.f; }
        if (r1 < NN) { float cnt = g_counts[batch[r1]]; s1 = (cnt > 0.f) ? (1.f / cnt) : 0.f; }
#pragma unroll
        for (int nf = 0; nf < 8; nf++) {
            int col = nbase + nf * 8 + t4 * 2;
            float b0 = __ldg(&brel[col]), b1 = __ldg(&brel[col + 1]);
            if (r0 < NN) {
                __half2 o = __floats2half2_rn((acc[mf][nf][0] + b0) * s0,
                                              (acc[mf][nf][1] + b1) * s0);
                *reinterpret_cast<__half2*>(out + (size_t)r0 * HH + col) = o;
            }
            if (r1 < NN) {
                __half2 o = __floats2half2_rn((acc[mf][nf][2] + b0) * s1,
                                              (acc[mf][nf][3] + b1) * s1);
                *reinterpret_cast<__half2*>(out + (size_t)r1 * HH + col) = o;
            }
        }
    }
}

// ---------------------------------------------------------------------------
// Fused head: mean-pool (fp16 in, fp32 accum), relu MLP, log_softmax.
// ---------------------------------------------------------------------------
__global__ void __launch_bounds__(HH)
head_kernel(int sel,
            const float* __restrict__ w1, const float* __restrict__ b1,
            const float* __restrict__ w2, const float* __restrict__ b2,
            float* __restrict__ out) {
    __shared__ float p[HH];
    __shared__ float hv[HH];
    __shared__ float lg[CC];
    __shared__ float m_s, ls_s;

    const int g = blockIdx.x;
    const int tid = threadIdx.x;
    const __half* h = sel_buf_h(sel);

    int lo = g_gstart[g], hi = g_gstart[g + 1];
    float inv = (hi > lo) ? (1.f / (float)(hi - lo)) : 0.f;
    float acc0 = 0.f;
    for (int r = lo; r < hi; r++) acc0 += __half2float(h[(size_t)r * HH + tid]);
    p[tid] = acc0 * inv;
    __syncthreads();

    float acc = b1[tid];
#pragma unroll 8
    for (int k = 0; k < HH; k++) acc += p[k] * w1[k * HH + tid];
    hv[tid] = fmaxf(acc, 0.f);
    __syncthreads();

    if (tid < CC) {
        float l = b2[tid];
#pragma unroll 8
        for (int k = 0; k < HH; k++) l += hv[k] * w2[k * CC + tid];
        lg[tid] = l;
    }
    __syncthreads();

    if (tid == 0) {
        float m = lg[0];
#pragma unroll
        for (int i = 1; i < CC; i++) m = fmaxf(m, lg[i]);
        float s = 0.f;
#pragma unroll
        for (int i = 0; i < CC; i++) s += expf(lg[i] - m);
        m_s = m;
        ls_s = logf(s);
    }
    __syncthreads();
    if (tid < CC) out[g * CC + tid] = lg[tid] - m_s - ls_s;
}

// ---------------------------------------------------------------------------
extern "C" void kernel_launch(void* const* d_in, const int* in_sizes, int n_in,
                              void* d_out, int out_size) {
    const float* x      = (const float*)d_in[0];
    const int*   ei     = (const int*)d_in[1];
    const int*   batch  = (const int*)d_in[2];
    const float* w_rel  = (const float*)d_in[3];
    const float* b_rel  = (const float*)d_in[4];
    const float* w_root = (const float*)d_in[5];
    const float* w1     = (const float*)d_in[6];
    const float* b1     = (const float*)d_in[7];
    const float* w2     = (const float*)d_in[8];
    const float* b2     = (const float*)d_in[9];
    float* out = (float*)d_out;

    // fp16 conversions (once per launch)
    convert_x_kernel<<<(NN * HH / 4 + 255) / 256, 256>>>(x);
    convert_w_kernel<<<(6 * HH * HH + 255) / 256, 256>>>(w_rel, w_root);

    // Graph bounds + counts (batch is sorted)
    bounds_kernel<<<1, GG>>>(batch);

    // CSR build (edge structure reused across 3 layers)
    zero_deg_kernel<<<(NN + 255) / 256, 256>>>();
    degree_kernel<<<(EE + 255) / 256, 256>>>(ei);
    scan1_kernel<<<SNB, SB>>>();
    scan2_kernel<<<1, 64>>>();
    scan3_kernel<<<SNB, SB>>>();
    fill_kernel<<<(EE + 255) / 256, 256>>>(ei);

    // 3 GraphConv layers (sel: -1 = x(fp16), 0 = g_h0, 1 = g_h1)
    int cur_sel = -1;
    for (int l = 0; l < LL; l++) {
        gather_kernel<<<(NN * 32 + 255) / 256, 256>>>(cur_sel);
        int out_sel = l & 1;
        gemm_layer_mma<<<GEMM_BLOCKS, 256>>>(cur_sel, out_sel, l,
                                             b_rel + (size_t)l * HH, batch);
        cur_sel = out_sel;
    }

    // Fused mean-pool + MLP head
    head_kernel<<<GG, HH>>>(cur_sel, w1, b1, w2, b2, out);
}